// round 2
// baseline (speedup 1.0000x reference)
#include <cuda_runtime.h>
#include <math.h>

#define NC 512
#define NPIX 1024

// ---------------- scratch (no allocations allowed) ----------------
__device__ float g_y[NC];                 // channel means
__device__ float g_s[NC];                 // SE scales
__device__ float g_A[32 * 32];            // row-stochastic gaussian matrix A[i][x]
__device__ float g_f0t[NPIX * NC];        // f0 transposed: [pix][ch]
__device__ float g_sigt[NPIX * NC];       // sigmoid(f0): [pix][ch]
__device__ float g_cat[2 * NPIX * NC];    // [0..512K): gus flat, [512K..1M): csa flat

#define FMA2(d, a, b) asm("fma.rn.f32x2 %0, %1, %2, %0;" : "+l"(d) : "l"(a), "l"(b))

// ---------------- 1. per-channel mean (blocks 0..511) + gaussian matrix A (block 512) ----------------
__global__ void k_mean_initA(const float* __restrict__ x) {
    int t = threadIdx.x;
    if (blockIdx.x < 512) {
        int c = blockIdx.x;
        float4 v = ((const float4*)(x + c * 1024))[t];
        float s = v.x + v.y + v.z + v.w;
        #pragma unroll
        for (int o = 16; o; o >>= 1) s += __shfl_down_sync(0xffffffffu, s, o);
        __shared__ float ws[8];
        if ((t & 31) == 0) ws[t >> 5] = s;
        __syncthreads();
        if (t == 0) {
            float tot = 0.f;
            #pragma unroll
            for (int i = 0; i < 8; i++) tot += ws[i];
            g_y[c] = tot * (1.f / 1024.f);
        }
    } else {
        __shared__ double srow[32];
        if (t < 32) {
            double s = 0.0;
            for (int xx = 0; xx < 32; xx++) {
                double d = (double)(xx - t);
                s += exp(-d * d / 4.5);
            }
            srow[t] = s;
        }
        __syncthreads();
        for (int idx = t; idx < 1024; idx += 256) {
            int i = idx >> 5, xx = idx & 31;
            double d = (double)(xx - i);
            g_A[idx] = (float)(exp(-d * d / 4.5) / srow[i]);
        }
    }
}

// ---------------- 2. SE MLP: 512 -> 32 (relu) -> 512 (sigmoid) ----------------
__global__ void k_mlp(const float* __restrict__ w1, const float* __restrict__ b1,
                      const float* __restrict__ w2, const float* __restrict__ b2) {
    __shared__ float sy[512];
    __shared__ float sh[32];
    int t = threadIdx.x;
    if (t < 512) sy[t] = g_y[t];
    __syncthreads();
    int r = t >> 5, lane = t & 31;   // 32 warps, one per hidden unit
    float a = 0.f;
    for (int c = lane; c < 512; c += 32) a += sy[c] * w1[r * 512 + c];
    #pragma unroll
    for (int o = 16; o; o >>= 1) a += __shfl_down_sync(0xffffffffu, a, o);
    if (lane == 0) sh[r] = fmaxf(a + b1[r], 0.f);
    __syncthreads();
    if (t < 512) {
        float acc = b2[t];
        #pragma unroll
        for (int rr = 0; rr < 32; rr++) acc += sh[rr] * w2[t * 32 + rr];
        g_s[t] = 1.f / (1.f + expf(-acc));
    }
}

// ---------------- 3. fused: gaussian pooling (blocks 0..511) + scale/transpose/sigmoid (512..1023) ----------------
__global__ void k_gauss_trans(const float* __restrict__ x) {
    __shared__ float sbuf[4096];
    int t = threadIdx.x;
    if (blockIdx.x < 512) {
        // --- separable gaussian pooling: B_c = A F_c A^T ---
        float* F   = sbuf;            // 1024
        float* T   = sbuf + 1024;     // 1024
        float* sA  = sbuf + 2048;     // 1024
        float* sAt = sbuf + 3072;     // 1024
        int c = blockIdx.x;
        float s = g_s[c];
        for (int i = t; i < 1024; i += 256) {
            F[i] = x[c * 1024 + i] * s;
            float a = g_A[i];
            sA[i] = a;                                // sA[k*32+y]  = A[k][y]
            sAt[(i & 31) * 32 + (i >> 5)] = a;        // sAt[y*32+k] = A[k][y]
        }
        __syncthreads();
        for (int idx = t; idx < 1024; idx += 256) {   // T[x][k] = sum_y A[k][y]*F[x][y]
            int xx = idx >> 5, k = idx & 31;
            float acc = 0.f;
            #pragma unroll
            for (int y = 0; y < 32; y++) acc += sAt[y * 32 + k] * F[xx * 32 + y];
            T[idx] = acc;
        }
        __syncthreads();
        for (int idx = t; idx < 1024; idx += 256) {   // B[i][k] = sum_x A[i][x]*T[x][k]
            int i = idx >> 5, k = idx & 31;
            float acc = 0.f;
            #pragma unroll
            for (int xx = 0; xx < 32; xx++) acc += sA[i * 32 + xx] * T[xx * 32 + k];
            g_cat[idx * 512 + c] = acc;
        }
    } else {
        // --- scale + transpose to pixel-major + sigmoid ---
        float (*tile)[33] = (float(*)[33])sbuf;
        int bid = blockIdx.x - 512;
        int p0 = (bid & 31) * 32, c0 = (bid >> 5) * 32;
        int tx = t & 31, ty = t >> 5;
        #pragma unroll
        for (int j = 0; j < 4; j++) {
            int ch = c0 + ty + j * 8;
            tile[ty + j * 8][tx] = x[ch * 1024 + p0 + tx] * g_s[ch];
        }
        __syncthreads();
        #pragma unroll
        for (int j = 0; j < 4; j++) {
            int p = p0 + ty + j * 8;
            float v = tile[tx][ty + j * 8];
            g_f0t[p * 512 + c0 + tx] = v;
            g_sigt[p * 512 + c0 + tx] = 1.f / (1.f + expf(-v));
        }
    }
}

// ---------------- 4. 3x3 patch-correlation attention (block per pixel) ----------------
__global__ void k_csa() {
    int pix = blockIdx.x, pi = pix >> 5, pj = pix & 31;
    int t = threadIdx.x;
    int c0 = t, c1 = t + 256;
    __shared__ float wsum[8][9];
    __shared__ float sa[9];
    float acc[9];
    int np[9];
    bool ok[9];
    float sc0 = g_sigt[pix * 512 + c0];
    float sc1 = g_sigt[pix * 512 + c1];
    #pragma unroll
    for (int uv = 0; uv < 9; uv++) {
        int u = uv / 3, v = uv % 3;
        int ni = pi + u - 1, nj = pj + v - 1;
        ok[uv] = (ni >= 0 && ni < 32 && nj >= 0 && nj < 32);
        np[uv] = ni * 32 + nj;
        acc[uv] = 0.f;
        if (ok[uv])
            acc[uv] = sc0 * g_sigt[np[uv] * 512 + c0] + sc1 * g_sigt[np[uv] * 512 + c1];
    }
    #pragma unroll
    for (int uv = 0; uv < 9; uv++)
        #pragma unroll
        for (int o = 16; o; o >>= 1) acc[uv] += __shfl_down_sync(0xffffffffu, acc[uv], o);
    if ((t & 31) == 0) {
        #pragma unroll
        for (int uv = 0; uv < 9; uv++) wsum[t >> 5][uv] = acc[uv];
    }
    __syncthreads();
    if (t == 0) {
        float av[9], m = -1e30f;
        #pragma unroll
        for (int uv = 0; uv < 9; uv++) {
            float s2 = 0.f;
            #pragma unroll
            for (int w = 0; w < 8; w++) s2 += wsum[w][uv];
            av[uv] = s2 * (1.f / 512.f);
            m = fmaxf(m, av[uv]);
        }
        float se = 0.f;
        #pragma unroll
        for (int uv = 0; uv < 9; uv++) { av[uv] = expf(av[uv] - m); se += av[uv]; }
        float inv = 1.f / se;
        #pragma unroll
        for (int uv = 0; uv < 9; uv++) sa[uv] = av[uv] * inv;
    }
    __syncthreads();
    float o0 = 0.f, o1 = 0.f;
    #pragma unroll
    for (int uv = 0; uv < 9; uv++) {
        if (ok[uv]) {
            float a = sa[uv];
            o0 += a * g_f0t[np[uv] * 512 + c0];
            o1 += a * g_f0t[np[uv] * 512 + c1];
        }
    }
    g_cat[524288 + pix * 512 + c0] = o0;
    g_cat[524288 + pix * 512 + c1] = o1;
}

// ---------------- 5. down GEMM with packed f32x2 FMA ----------------
// z[512,1024] = W[512,1024] @ cat[1024,1024]; 64x64 tiles, Ktile=32.
__global__ void k_gemm(const float* __restrict__ Wd, float* __restrict__ out) {
    __shared__ float2 As2[32][64];   // duplicated pairs: As2[k][m] = (a, a)
    __shared__ float  Bs[32][64];    // Bs[k][n]
    int t = threadIdx.x;
    int tx = t & 15, ty = t >> 4;
    int m0 = blockIdx.y * 64, n0 = blockIdx.x * 64;
    unsigned long long acc[4][2];
    #pragma unroll
    for (int i = 0; i < 4; i++) { acc[i][0] = 0ull; acc[i][1] = 0ull; }

    for (int k0 = 0; k0 < 1024; k0 += 32) {
        __syncthreads();
        #pragma unroll
        for (int q = t; q < 512; q += 256) {       // A tile: 64 rows x 32 k
            int m = q >> 3, kk = (q & 7) * 4;
            float4 w = *(const float4*)(Wd + (m0 + m) * 1024 + k0 + kk);
            As2[kk + 0][m] = make_float2(w.x, w.x);
            As2[kk + 1][m] = make_float2(w.y, w.y);
            As2[kk + 2][m] = make_float2(w.z, w.z);
            As2[kk + 3][m] = make_float2(w.w, w.w);
        }
        #pragma unroll
        for (int q = t; q < 512; q += 256) {       // B tile: 32 k x 64 n
            int kk = q >> 4, nn = (q & 15) * 4;
            *(float4*)&Bs[kk][nn] = *(const float4*)(g_cat + (k0 + kk) * 1024 + n0 + nn);
        }
        __syncthreads();
        #pragma unroll
        for (int k = 0; k < 32; k++) {
            ulonglong2 aA = *(ulonglong2*)&As2[k][ty * 4];       // (a0,a0),(a1,a1)
            ulonglong2 aB = *(ulonglong2*)&As2[k][ty * 4 + 2];   // (a2,a2),(a3,a3)
            ulonglong2 bb = *(ulonglong2*)&Bs[k][tx * 4];        // (b0,b1),(b2,b3)
            FMA2(acc[0][0], aA.x, bb.x); FMA2(acc[0][1], aA.x, bb.y);
            FMA2(acc[1][0], aA.y, bb.x); FMA2(acc[1][1], aA.y, bb.y);
            FMA2(acc[2][0], aB.x, bb.x); FMA2(acc[2][1], aB.x, bb.y);
            FMA2(acc[3][0], aB.y, bb.x); FMA2(acc[3][1], aB.y, bb.y);
        }
    }
    #pragma unroll
    for (int i = 0; i < 4; i++) {
        float2 lo = *(float2*)&acc[i][0];
        float2 hi = *(float2*)&acc[i][1];
        *(float4*)(out + (m0 + ty * 4 + i) * 1024 + n0 + tx * 4) =
            make_float4(lo.x, lo.y, hi.x, hi.y);
    }
}

// ---------------- 6. instance norm + leaky relu (in place) ----------------
__global__ void k_norm(float* __restrict__ out) {
    int o = blockIdx.x, t = threadIdx.x;
    float4* row = (float4*)(out + o * 1024);
    float4 v = row[t];
    float s = v.x + v.y + v.z + v.w;
    float ss = v.x * v.x + v.y * v.y + v.z * v.z + v.w * v.w;
    #pragma unroll
    for (int off = 16; off; off >>= 1) {
        s  += __shfl_down_sync(0xffffffffu, s, off);
        ss += __shfl_down_sync(0xffffffffu, ss, off);
    }
    __shared__ float w1s[8], w2s[8];
    __shared__ float smean, sinv;
    if ((t & 31) == 0) { w1s[t >> 5] = s; w2s[t >> 5] = ss; }
    __syncthreads();
    if (t == 0) {
        float ts = 0.f, tss = 0.f;
        #pragma unroll
        for (int i = 0; i < 8; i++) { ts += w1s[i]; tss += w2s[i]; }
        float mu = ts * (1.f / 1024.f);
        float var = tss * (1.f / 1024.f) - mu * mu;
        smean = mu;
        sinv = 1.f / sqrtf(var + 1e-5f);
    }
    __syncthreads();
    float mu = smean, inv = sinv;
    float a;
    a = (v.x - mu) * inv; v.x = a >= 0.f ? a : 0.2f * a;
    a = (v.y - mu) * inv; v.y = a >= 0.f ? a : 0.2f * a;
    a = (v.z - mu) * inv; v.z = a >= 0.f ? a : 0.2f * a;
    a = (v.w - mu) * inv; v.w = a >= 0.f ? a : 0.2f * a;
    row[t] = v;
}

// ---------------- launch ----------------
extern "C" void kernel_launch(void* const* d_in, const int* in_sizes, int n_in,
                              void* d_out, int out_size) {
    const float* x  = (const float*)d_in[0];   // (1,512,32,32)
    const float* w1 = (const float*)d_in[1];   // (32,512)
    const float* b1 = (const float*)d_in[2];   // (32)
    const float* w2 = (const float*)d_in[3];   // (512,32)
    const float* b2 = (const float*)d_in[4];   // (512)
    const float* dw = (const float*)d_in[5];   // (512,1024)
    float* out = (float*)d_out;                // (1,512,32,32) fp32

    k_mean_initA<<<513, 256>>>(x);
    k_mlp<<<1, 1024>>>(w1, b1, w2, b2);
    k_gauss_trans<<<1024, 256>>>(x);
    k_csa<<<1024, 256>>>();
    k_gemm<<<dim3(16, 8), 256>>>(dw, out);
    k_norm<<<512, 256>>>(out);
}